// round 3
// baseline (speedup 1.0000x reference)
#include <cuda_runtime.h>

#define S 64
#define NB 8
#define C 256
#define CR 64
#define P 4096   // S*S per plane

// ---- scratch (device globals; no runtime allocation allowed) ----
__device__ float g_red[NB * CR * P];     // 8 MB
__device__ float g_u  [NB * C  * P];     // 32 MB
__device__ float g_lam[NB * C  * P];     // 32 MB
__device__ float g_Rv [NB * P];          // 128 KB
__device__ float g_A  [NB * C  * P];     // 32 MB
__device__ float g_Bt [NB * C  * P];     // 32 MB
__device__ float g_Wfold[256 * 512];     // 512 KB

// ============================================================
// Fold merge weights: Wfold[o,k] = wm[o,k] + wm[o,k+512], k<512
// (concat channel blocks are [A;B;A;B], so blocks 0/2 and 1/3 fold)
// ============================================================
__global__ void k_fold(const float* __restrict__ wm) {
    int i = blockIdx.x * 256 + threadIdx.x;   // 131072 elems
    int o = i >> 9, k = i & 511;
    g_Wfold[i] = wm[o * 1024 + k] + wm[o * 1024 + k + 512];
}

// ============================================================
// K1: reduced[b,m,p] = sum_k w_red[m,k]*x[b,k,p] + b_red[m]
// M=64, K=256, N=4096/batch.  Tile 64x128, BK=32, 256 thr, 4x8 micro.
// ============================================================
__global__ __launch_bounds__(256) void k_red(const float* __restrict__ x,
                                             const float* __restrict__ w,
                                             const float* __restrict__ bias) {
    __shared__ float As[32][64];    // [k][m]
    __shared__ float Bs[32][128];   // [k][p]
    int b  = blockIdx.z;
    int p0 = blockIdx.x * 128;
    int tid = threadIdx.x;
    int mb = (tid >> 4) * 4;
    int nb = (tid & 15) * 8;
    float acc[4][8];
#pragma unroll
    for (int i = 0; i < 4; i++)
#pragma unroll
        for (int j = 0; j < 8; j++) acc[i][j] = 0.f;

    const float* xb = x + (size_t)b * C * P;
    for (int k0 = 0; k0 < 256; k0 += 32) {
#pragma unroll
        for (int l = 0; l < 2; l++) {               // 64 rows x 32 k
            int fid = tid + l * 256;
            int row = fid >> 3, kq = fid & 7;
            float4 v = *(const float4*)(w + row * 256 + k0 + kq * 4);
            As[kq * 4 + 0][row] = v.x; As[kq * 4 + 1][row] = v.y;
            As[kq * 4 + 2][row] = v.z; As[kq * 4 + 3][row] = v.w;
        }
#pragma unroll
        for (int l = 0; l < 4; l++) {               // 32 k x 128 p
            int fid = tid + l * 256;
            int kk = fid >> 5, pq = fid & 31;
            *(float4*)&Bs[kk][pq * 4] =
                *(const float4*)(xb + (size_t)(k0 + kk) * P + p0 + pq * 4);
        }
        __syncthreads();
#pragma unroll
        for (int kk = 0; kk < 32; kk++) {
            float4 a  = *(float4*)&As[kk][mb];
            float4 b0 = *(float4*)&Bs[kk][nb];
            float4 b1 = *(float4*)&Bs[kk][nb + 4];
            float av[4] = {a.x, a.y, a.z, a.w};
            float bv[8] = {b0.x, b0.y, b0.z, b0.w, b1.x, b1.y, b1.z, b1.w};
#pragma unroll
            for (int i = 0; i < 4; i++)
#pragma unroll
                for (int j = 0; j < 8; j++) acc[i][j] += av[i] * bv[j];
        }
        __syncthreads();
    }
#pragma unroll
    for (int i = 0; i < 4; i++) {
        int m = mb + i;
        float bs = bias[m];
        float* dst = g_red + ((size_t)b * CR + m) * P + p0 + nb;
        float4 o0 = {acc[i][0] + bs, acc[i][1] + bs, acc[i][2] + bs, acc[i][3] + bs};
        float4 o1 = {acc[i][4] + bs, acc[i][5] + bs, acc[i][6] + bs, acc[i][7] + bs};
        *(float4*)(dst)     = o0;
        *(float4*)(dst + 4) = o1;
    }
}

// ============================================================
// K2: u (rows 0..255) and lam (rows 256..511) from reduced.
// M=512, K=64, N=4096/batch.  Tile 128x128, BK=32, 8x8 micro.
// ============================================================
__global__ __launch_bounds__(256) void k_ul(const float* __restrict__ wu,
                                            const float* __restrict__ bu,
                                            const float* __restrict__ wl,
                                            const float* __restrict__ bl) {
    __shared__ float As[32][128];   // [k][m]
    __shared__ float Bs[32][128];   // [k][p]
    int b  = blockIdx.z;
    int m0 = blockIdx.y * 128;
    int p0 = blockIdx.x * 128;
    int tid = threadIdx.x;
    int mb = (tid >> 4) * 8;
    int nb = (tid & 15) * 8;
    float acc[8][8];
#pragma unroll
    for (int i = 0; i < 8; i++)
#pragma unroll
        for (int j = 0; j < 8; j++) acc[i][j] = 0.f;

    const float* red = g_red + (size_t)b * CR * P;
    for (int k0 = 0; k0 < 64; k0 += 32) {
#pragma unroll
        for (int l = 0; l < 4; l++) {               // 128 rows x 32 k
            int fid = tid + l * 256;
            int row = fid >> 3, kq = fid & 7;
            int mg = m0 + row;
            const float* wrow = (mg < 256) ? (wu + mg * 64) : (wl + (mg - 256) * 64);
            float4 v = *(const float4*)(wrow + k0 + kq * 4);
            As[kq * 4 + 0][row] = v.x; As[kq * 4 + 1][row] = v.y;
            As[kq * 4 + 2][row] = v.z; As[kq * 4 + 3][row] = v.w;
        }
#pragma unroll
        for (int l = 0; l < 4; l++) {               // 32 k x 128 p
            int fid = tid + l * 256;
            int kk = fid >> 5, pq = fid & 31;
            *(float4*)&Bs[kk][pq * 4] =
                *(const float4*)(red + (size_t)(k0 + kk) * P + p0 + pq * 4);
        }
        __syncthreads();
#pragma unroll
        for (int kk = 0; kk < 32; kk++) {
            float4 a0 = *(float4*)&As[kk][mb];
            float4 a1 = *(float4*)&As[kk][mb + 4];
            float4 b0 = *(float4*)&Bs[kk][nb];
            float4 b1 = *(float4*)&Bs[kk][nb + 4];
            float av[8] = {a0.x, a0.y, a0.z, a0.w, a1.x, a1.y, a1.z, a1.w};
            float bv[8] = {b0.x, b0.y, b0.z, b0.w, b1.x, b1.y, b1.z, b1.w};
#pragma unroll
            for (int i = 0; i < 8; i++)
#pragma unroll
                for (int j = 0; j < 8; j++) acc[i][j] += av[i] * bv[j];
        }
        __syncthreads();
    }
#pragma unroll
    for (int i = 0; i < 8; i++) {
        int mg = m0 + mb + i;
        float bs;
        float* dst;
        if (mg < 256) { bs = bu[mg]; dst = g_u  + ((size_t)b * C + mg)       * P; }
        else          { bs = bl[mg - 256]; dst = g_lam + ((size_t)b * C + mg - 256) * P; }
        dst += p0 + nb;
        float4 o0 = {acc[i][0] + bs, acc[i][1] + bs, acc[i][2] + bs, acc[i][3] + bs};
        float4 o1 = {acc[i][4] + bs, acc[i][5] + bs, acc[i][6] + bs, acc[i][7] + bs};
        *(float4*)(dst)     = o0;
        *(float4*)(dst + 4) = o1;
    }
}

// ============================================================
// K3: pre (3ch) from reduced, sigmoid, normalize, band-validity sum.
// Rv[b,h,w] = (s1 + (w>=1)s0 + (w<=S-2)s2) / max(s0+s1+s2, 1e-6)
// ============================================================
__global__ __launch_bounds__(256) void k_rv(const float* __restrict__ wwt,
                                            const float* __restrict__ bwt) {
    __shared__ float ws[192];
    __shared__ float bs[3];
    int tid = threadIdx.x;
    if (tid < 192) ws[tid] = wwt[tid];
    if (tid < 3)   bs[tid] = bwt[tid];
    __syncthreads();
    int gid = blockIdx.x * 256 + tid;       // 32768 pixels
    int b = gid >> 12, p = gid & 4095, w = p & 63;
    const float* red = g_red + (size_t)b * CR * P + p;
    float a0 = bs[0], a1 = bs[1], a2 = bs[2];
#pragma unroll 8
    for (int c = 0; c < 64; c++) {
        float r = red[(size_t)c * P];
        a0 += ws[c]       * r;
        a1 += ws[64 + c]  * r;
        a2 += ws[128 + c] * r;
    }
    float s0 = 1.f / (1.f + expf(-a0));
    float s1 = 1.f / (1.f + expf(-a1));
    float s2 = 1.f / (1.f + expf(-a2));
    float den = fmaxf(s0 + s1 + s2, 1e-6f);
    float rv = s1;
    if (w >= 1)     rv += s0;
    if (w <= S - 2) rv += s2;
    g_Rv[gid] = rv / den;
}

// ============================================================
// K4: fused dual linear-recurrence scan along w (warp-parallel).
// One block per (b,c) plane. 16 warps, each scans 4 rows (h).
//   A: h_w = h*Rv[b,h,w] + lam[b,c,w,h]*x       ; out A = h*u[b,c,h,w]
//   B: h_w = h*Rv[b,h,w] + lam[b,c,63-w,63-h]*x ; out B = h*u[b,c,63-h,w]
// lam plane staged in padded smem (stride 65) for the transposed reads.
// Both scans share coefficient 'a' -> one shared a-component in composite.
// ============================================================
__global__ __launch_bounds__(512) void k_scan(const float* __restrict__ x) {
    __shared__ float ls[64 * 65];
    int b = blockIdx.y, c = blockIdx.x;
    size_t base = ((size_t)b * C + c) * P;
    const float* xp = x + base;
    const float* up = g_u + base;
    const float* lp = g_lam + base;
    const float* rv = g_Rv + (size_t)b * P;
    float* Ap = g_A + base;
    float* Bp = g_Bt + base;
    int tid = threadIdx.x;

#pragma unroll
    for (int l = 0; l < 2; l++) {           // 1024 float4s of lam plane
        int fid = tid + l * 512;
        int row = fid >> 4, q = fid & 15;
        float4 v = *(const float4*)(lp + row * 64 + q * 4);
        ls[row * 65 + q * 4 + 0] = v.x;
        ls[row * 65 + q * 4 + 1] = v.y;
        ls[row * 65 + q * 4 + 2] = v.z;
        ls[row * 65 + q * 4 + 3] = v.w;
    }
    __syncthreads();

    int wid = tid >> 5, lane = tid & 31;
#pragma unroll
    for (int r = 0; r < 4; r++) {
        int h = wid + r * 16;
        int hb = 63 - h;
        int w0 = lane * 2, w1 = w0 + 1;
        float2 av = *(const float2*)(rv + h * 64 + w0);
        float a0 = av.x, a1 = av.y;
        float2 xv = *(const float2*)(xp + h * 64 + w0);
        float bA0 = ls[w0 * 65 + h] * xv.x;
        float bA1 = ls[w1 * 65 + h] * xv.y;
        float bB0 = ls[(63 - w0) * 65 + hb] * xv.x;
        float bB1 = ls[(63 - w1) * 65 + hb] * xv.y;
        // local pair composite (apply w0 then w1)
        float ca  = a0 * a1;
        float cbA = a1 * bA0 + bA1;
        float cbB = a1 * bB0 + bB1;
        // warp inclusive scan: combine(prev, cur) = (pa*ca, ca*pb + cb)
#pragma unroll
        for (int d = 1; d < 32; d <<= 1) {
            float pa  = __shfl_up_sync(0xffffffffu, ca,  d);
            float pbA = __shfl_up_sync(0xffffffffu, cbA, d);
            float pbB = __shfl_up_sync(0xffffffffu, cbB, d);
            if (lane >= d) {
                cbA = ca * pbA + cbA;
                cbB = ca * pbB + cbB;
                ca  = ca * pa;
            }
        }
        float eA = __shfl_up_sync(0xffffffffu, cbA, 1);
        float eB = __shfl_up_sync(0xffffffffu, cbB, 1);
        if (lane == 0) { eA = 0.f; eB = 0.f; }
        float hA0 = a0 * eA + bA0;
        float hA1 = a1 * hA0 + bA1;
        float hB0 = a0 * eB + bB0;
        float hB1 = a1 * hB0 + bB1;
        float2 uv  = *(const float2*)(up + h  * 64 + w0);
        float2 uvb = *(const float2*)(up + hb * 64 + w0);
        float2 oA = {hA0 * uv.x,  hA1 * uv.y};
        float2 oB = {hB0 * uvb.x, hB1 * uvb.y};
        *(float2*)(Ap + h * 64 + w0) = oA;
        *(float2*)(Bp + h * 64 + w0) = oB;
    }
}

// ============================================================
// K5: out[b,o,p] = sum_{k<512} Wfold[o,k]*Kmat[b,k,p] + b_merge[o]
//   Kmat row k: k<256 -> A plane k ; else B plane k-256.
// M=256, K=512, N=4096/batch.  Tile 128x128, BK=16, 8x8 micro.
// ============================================================
__global__ __launch_bounds__(256) void k_merge(float* __restrict__ out,
                                               const float* __restrict__ bm) {
    __shared__ float As[16][128];   // [k][m]
    __shared__ float Bs[16][128];   // [k][p]
    int b  = blockIdx.z;
    int m0 = blockIdx.y * 128;
    int p0 = blockIdx.x * 128;
    int tid = threadIdx.x;
    int mb = (tid >> 4) * 8;
    int nb = (tid & 15) * 8;
    float acc[8][8];
#pragma unroll
    for (int i = 0; i < 8; i++)
#pragma unroll
        for (int j = 0; j < 8; j++) acc[i][j] = 0.f;

    const float* Ab = g_A  + (size_t)b * C * P;
    const float* Bb = g_Bt + (size_t)b * C * P;
    for (int k0 = 0; k0 < 512; k0 += 16) {
#pragma unroll
        for (int l = 0; l < 2; l++) {               // 128 rows x 16 k
            int fid = tid + l * 256;
            int row = fid >> 2, kq = fid & 3;
            float4 v = *(const float4*)(g_Wfold + (size_t)(m0 + row) * 512 + k0 + kq * 4);
            As[kq * 4 + 0][row] = v.x; As[kq * 4 + 1][row] = v.y;
            As[kq * 4 + 2][row] = v.z; As[kq * 4 + 3][row] = v.w;
        }
#pragma unroll
        for (int l = 0; l < 2; l++) {               // 16 k x 128 p
            int fid = tid + l * 256;
            int kk = fid >> 5, pq = fid & 31;
            int kg = k0 + kk;
            const float* src = (kg < 256) ? (Ab + (size_t)kg * P)
                                          : (Bb + (size_t)(kg - 256) * P);
            *(float4*)&Bs[kk][pq * 4] = *(const float4*)(src + p0 + pq * 4);
        }
        __syncthreads();
#pragma unroll
        for (int kk = 0; kk < 16; kk++) {
            float4 a0 = *(float4*)&As[kk][mb];
            float4 a1 = *(float4*)&As[kk][mb + 4];
            float4 b0 = *(float4*)&Bs[kk][nb];
            float4 b1 = *(float4*)&Bs[kk][nb + 4];
            float av[8] = {a0.x, a0.y, a0.z, a0.w, a1.x, a1.y, a1.z, a1.w};
            float bv[8] = {b0.x, b0.y, b0.z, b0.w, b1.x, b1.y, b1.z, b1.w};
#pragma unroll
            for (int i = 0; i < 8; i++)
#pragma unroll
                for (int j = 0; j < 8; j++) acc[i][j] += av[i] * bv[j];
        }
        __syncthreads();
    }
#pragma unroll
    for (int i = 0; i < 8; i++) {
        int o = m0 + mb + i;
        float bs = bm[o];
        float* dst = out + ((size_t)b * C + o) * P + p0 + nb;
        float4 o0 = {acc[i][0] + bs, acc[i][1] + bs, acc[i][2] + bs, acc[i][3] + bs};
        float4 o1 = {acc[i][4] + bs, acc[i][5] + bs, acc[i][6] + bs, acc[i][7] + bs};
        *(float4*)(dst)     = o0;
        *(float4*)(dst + 4) = o1;
    }
}

// ============================================================
extern "C" void kernel_launch(void* const* d_in, const int* in_sizes, int n_in,
                              void* d_out, int out_size) {
    const float* x       = (const float*)d_in[0];
    const float* w_red   = (const float*)d_in[1];
    const float* b_red   = (const float*)d_in[2];
    const float* w_u     = (const float*)d_in[3];
    const float* b_u     = (const float*)d_in[4];
    const float* w_lam   = (const float*)d_in[5];
    const float* b_lam   = (const float*)d_in[6];
    const float* w_wt    = (const float*)d_in[7];
    const float* b_wt    = (const float*)d_in[8];
    const float* w_merge = (const float*)d_in[9];
    const float* b_merge = (const float*)d_in[10];
    float* out = (float*)d_out;

    k_fold<<<512, 256>>>(w_merge);
    k_red <<<dim3(32, 1, NB), 256>>>(x, w_red, b_red);
    k_ul  <<<dim3(32, 4, NB), 256>>>(w_u, b_u, w_lam, b_lam);
    k_rv  <<<128, 256>>>(w_wt, b_wt);
    k_scan<<<dim3(256, NB), 512>>>(x);
    k_merge<<<dim3(32, 2, NB), 256>>>(out, b_merge);
}